// round 1
// baseline (speedup 1.0000x reference)
#include <cuda_runtime.h>
#include <cuda_bf16.h>
#include <mma.h>
#include <math.h>

using namespace nvcuda;

#define BATCH   2
#define SEQ     2048
#define DMODEL  2048
#define HEADS   16
#define DKH     128
#define MROWS   (BATCH*SEQ)

// Scratch (allocation-free rule: __device__ globals)
__device__ float g_Q[BATCH*HEADS*SEQ*DKH];   // [b,h,s,d]
__device__ float g_K[BATCH*HEADS*SEQ*DKH];
__device__ float g_V[BATCH*HEADS*SEQ*DKH];
__device__ float g_AO[BATCH*SEQ*DMODEL];     // attention output, [b,s,D]

// ---------------------------------------------------------------------------
// tf32 WMMA GEMM:  C[m,n] = sum_k A[m,k] * W[n,k]
// A: [M,2048] row-major fp32, W: [2048,2048] row-major fp32 (used as B col-major)
// HEADWISE=true: scatter output to [b,h,s,dk] layout (block N-tile == one head)
// ---------------------------------------------------------------------------
template<bool HEADWISE>
__global__ __launch_bounds__(256)
void gemm_tf32(const float* __restrict__ A, const float* __restrict__ W,
               float* __restrict__ C)
{
    __shared__ float As[128*36];   // [m][k], lda=36
    __shared__ float Bs[128*36];   // [n][k], -> col_major k x n with ldb=36

    const int m0  = blockIdx.y * 128;
    const int n0  = blockIdx.x * 128;
    const int tid = threadIdx.x;
    const int wid = tid >> 5;
    const int wm  = wid & 1;       // 2 warp rows
    const int wn  = wid >> 1;      // 4 warp cols

    wmma::fragment<wmma::accumulator,16,16,8,float> c[4][2];
#pragma unroll
    for (int i = 0; i < 4; i++)
#pragma unroll
        for (int j = 0; j < 2; j++)
            wmma::fill_fragment(c[i][j], 0.0f);

    for (int kt = 0; kt < 2048; kt += 32) {
        // load A tile 128x32 (1024 float4, 4 per thread)
#pragma unroll
        for (int it = 0; it < 4; it++) {
            int idx = it*256 + tid;
            int row = idx >> 3, c4 = idx & 7;
            float4 v = *(const float4*)(A + (size_t)(m0+row)*2048 + kt + c4*4);
            float* d = &As[row*36 + c4*4];
            d[0] = wmma::__float_to_tf32(v.x);
            d[1] = wmma::__float_to_tf32(v.y);
            d[2] = wmma::__float_to_tf32(v.z);
            d[3] = wmma::__float_to_tf32(v.w);
        }
        // load W tile 128x32 into Bs[n][k]
#pragma unroll
        for (int it = 0; it < 4; it++) {
            int idx = it*256 + tid;
            int row = idx >> 3, c4 = idx & 7;
            float4 v = *(const float4*)(W + (size_t)(n0+row)*2048 + kt + c4*4);
            float* d = &Bs[row*36 + c4*4];
            d[0] = wmma::__float_to_tf32(v.x);
            d[1] = wmma::__float_to_tf32(v.y);
            d[2] = wmma::__float_to_tf32(v.z);
            d[3] = wmma::__float_to_tf32(v.w);
        }
        __syncthreads();

#pragma unroll
        for (int ks = 0; ks < 4; ks++) {
            wmma::fragment<wmma::matrix_a,16,16,8,wmma::precision::tf32,wmma::row_major> a[4];
            wmma::fragment<wmma::matrix_b,16,16,8,wmma::precision::tf32,wmma::col_major> b[2];
#pragma unroll
            for (int i = 0; i < 4; i++)
                wmma::load_matrix_sync(a[i], &As[(wm*64 + i*16)*36 + ks*8], 36);
#pragma unroll
            for (int j = 0; j < 2; j++)
                wmma::load_matrix_sync(b[j], &Bs[(wn*32 + j*16)*36 + ks*8], 36);
#pragma unroll
            for (int i = 0; i < 4; i++)
#pragma unroll
                for (int j = 0; j < 2; j++)
                    wmma::mma_sync(c[i][j], a[i], b[j], c[i][j]);
        }
        __syncthreads();
    }

    if (HEADWISE) {
        // n-tile == one head (128 cols), m never straddles batch (2048 % 128 == 0)
        const int b  = m0 / SEQ;
        const int s0 = m0 % SEQ;
        const int h  = blockIdx.x;            // n0 / 128
        float* base = C + ((size_t)(b*HEADS + h)*SEQ + s0) * DKH;
#pragma unroll
        for (int i = 0; i < 4; i++)
#pragma unroll
            for (int j = 0; j < 2; j++)
                wmma::store_matrix_sync(base + (size_t)(wm*64 + i*16)*DKH + wn*32 + j*16,
                                        c[i][j], DKH, wmma::mem_row_major);
    } else {
        float* base = C + (size_t)m0*DMODEL + n0;
#pragma unroll
        for (int i = 0; i < 4; i++)
#pragma unroll
            for (int j = 0; j < 2; j++)
                wmma::store_matrix_sync(base + (size_t)(wm*64 + i*16)*DMODEL + wn*32 + j*16,
                                        c[i][j], DMODEL, wmma::mem_row_major);
    }
}

// ---------------------------------------------------------------------------
// RoPE in place on [b,h,s,dk] tensor. positions == s by construction.
// ---------------------------------------------------------------------------
__global__ void rope_kernel(float* __restrict__ X)
{
    int idx = blockIdx.x * blockDim.x + threadIdx.x;   // pair index
    // total pairs = 32 * 2048 * 64
    if (idx >= BATCH*HEADS*SEQ*(DKH/2)) return;
    int dd = idx & 63;
    int s  = (idx >> 6) & (SEQ - 1);
    float freq = exp2f(-13.287712379549449f * ((float)(2*dd) * (1.0f/128.0f))); // theta^{-2j/dk}
    float ang  = (float)s * freq;
    float sn, cs;
    sincosf(ang, &sn, &cs);
    float* p = X + (size_t)idx * 2;
    float x1 = p[0], x2 = p[1];
    p[0] = x1*cs - x2*sn;
    p[1] = x1*sn + x2*cs;
}

// ---------------------------------------------------------------------------
// Flash attention (causal), fp32. Br=Bc=64, d=128. One CTA per (q-tile, b*h).
// smem: QsT[128][68], KsT[128][68] (transposed for conflict-free dot loop),
//       Vs[64][132], Ss[64][68], row stats.
// ---------------------------------------------------------------------------
#define FPAD  68
#define VPAD  132
#define FLASH_SMEM_FLOATS (128*FPAD*2 + 64*VPAD + 64*FPAD + 3*64)

__global__ __launch_bounds__(256)
void flash_kernel(const float* __restrict__ Q, const float* __restrict__ K,
                  const float* __restrict__ V, float* __restrict__ O)
{
    extern __shared__ float sm[];
    float* QsT  = sm;                         // [k][i]  128*68
    float* KsT  = QsT + 128*FPAD;             // [k][j]  128*68
    float* Vs   = KsT + 128*FPAD;             // [j][d]  64*132
    float* Ss   = Vs  + 64*VPAD;              // [i][j]  64*68
    float* row_m  = Ss + 64*FPAD;
    float* row_l  = row_m + 64;
    float* row_al = row_l + 64;

    const int qt  = gridDim.x - 1 - blockIdx.x;     // heavy tiles first
    const int bh  = blockIdx.y;
    const int b   = bh >> 4;
    const int h   = bh & 15;
    const int q0  = qt * 64;
    const int tid = threadIdx.x;
    const int ty  = tid >> 4;                  // 0..15
    const int tx  = tid & 15;                  // 0..15

    // ---- load Q tile transposed
    const float* Qb = Q + ((size_t)bh * SEQ + q0) * DKH;
    for (int i = tid; i < 64*32; i += 256) {
        int r = i >> 5, c4 = i & 31;
        float4 v = *(const float4*)(Qb + (size_t)r*DKH + c4*4);
        QsT[(c4*4+0)*FPAD + r] = v.x;
        QsT[(c4*4+1)*FPAD + r] = v.y;
        QsT[(c4*4+2)*FPAD + r] = v.z;
        QsT[(c4*4+3)*FPAD + r] = v.w;
    }
    if (tid < 64) { row_m[tid] = -INFINITY; row_l[tid] = 0.0f; }

    float acc[4][8];
#pragma unroll
    for (int i = 0; i < 4; i++)
#pragma unroll
        for (int c = 0; c < 8; c++) acc[i][c] = 0.0f;

    const float SCALE = 0.08838834764831845f;   // 1/sqrt(128)
    const int ntiles = qt + 1;

    for (int t = 0; t < ntiles; t++) {
        const int k0 = t * 64;
        __syncthreads();   // prev iteration's consumers done before overwrite
        const float* Kb = K + ((size_t)bh * SEQ + k0) * DKH;
        const float* Vb = V + ((size_t)bh * SEQ + k0) * DKH;
        for (int i = tid; i < 64*32; i += 256) {
            int r = i >> 5, c4 = i & 31;
            float4 kv = *(const float4*)(Kb + (size_t)r*DKH + c4*4);
            KsT[(c4*4+0)*FPAD + r] = kv.x;
            KsT[(c4*4+1)*FPAD + r] = kv.y;
            KsT[(c4*4+2)*FPAD + r] = kv.z;
            KsT[(c4*4+3)*FPAD + r] = kv.w;
            float4 vv = *(const float4*)(Vb + (size_t)r*DKH + c4*4);
            *(float4*)&Vs[r*VPAD + c4*4] = vv;
        }
        __syncthreads();

        // ---- phase 1: S = Q K^T (4x4 per thread)
        float sa[4][4];
#pragma unroll
        for (int i = 0; i < 4; i++)
#pragma unroll
            for (int j = 0; j < 4; j++) sa[i][j] = 0.0f;

#pragma unroll 4
        for (int k = 0; k < DKH; k++) {
            float qr[4], kr[4];
#pragma unroll
            for (int i = 0; i < 4; i++) qr[i] = QsT[k*FPAD + ty*4 + i];
#pragma unroll
            for (int j = 0; j < 4; j++) kr[j] = KsT[k*FPAD + tx*4 + j];
#pragma unroll
            for (int i = 0; i < 4; i++)
#pragma unroll
                for (int j = 0; j < 4; j++)
                    sa[i][j] = fmaf(qr[i], kr[j], sa[i][j]);
        }
        const bool diag = (t == ntiles - 1) && (k0 == q0);
#pragma unroll
        for (int i = 0; i < 4; i++) {
            int gi = ty*4 + i;
#pragma unroll
            for (int j = 0; j < 4; j++) {
                int gj = tx*4 + j;
                float sv = sa[i][j] * SCALE;
                if (diag && (gj > gi)) sv = -INFINITY;
                Ss[gi*FPAD + gj] = sv;
            }
        }
        __syncthreads();

        // ---- phase 2: online softmax (4 threads per row, 16 cols each)
        {
            int r   = tid >> 2;
            int seg = tid & 3;
            float vals[16];
            float lm = -INFINITY;
#pragma unroll
            for (int j = 0; j < 16; j++) {
                vals[j] = Ss[r*FPAD + seg*16 + j];
                lm = fmaxf(lm, vals[j]);
            }
            lm = fmaxf(lm, __shfl_xor_sync(0xffffffffu, lm, 1));
            lm = fmaxf(lm, __shfl_xor_sync(0xffffffffu, lm, 2));
            float m_old = row_m[r];
            float m_new = fmaxf(m_old, lm);
            float lsum = 0.0f;
#pragma unroll
            for (int j = 0; j < 16; j++) {
                float p = __expf(vals[j] - m_new);
                Ss[r*FPAD + seg*16 + j] = p;
                lsum += p;
            }
            lsum += __shfl_xor_sync(0xffffffffu, lsum, 1);
            lsum += __shfl_xor_sync(0xffffffffu, lsum, 2);
            if (seg == 0) {
                float al = __expf(m_old - m_new);
                row_al[r] = al;
                row_m[r]  = m_new;
                row_l[r]  = row_l[r] * al + lsum;
            }
        }
        __syncthreads();

        // ---- phase 3: O = O*alpha + P V  (rows ty*4.., cols tx*8..)
#pragma unroll
        for (int i = 0; i < 4; i++) {
            float al = row_al[ty*4 + i];
#pragma unroll
            for (int c = 0; c < 8; c++) acc[i][c] *= al;
        }
#pragma unroll 2
        for (int j = 0; j < 64; j++) {
            float pr[4];
#pragma unroll
            for (int i = 0; i < 4; i++) pr[i] = Ss[(ty*4 + i)*FPAD + j];
            float4 v0 = *(const float4*)&Vs[j*VPAD + tx*8];
            float4 v1 = *(const float4*)&Vs[j*VPAD + tx*8 + 4];
            float vv[8] = {v0.x, v0.y, v0.z, v0.w, v1.x, v1.y, v1.z, v1.w};
#pragma unroll
            for (int i = 0; i < 4; i++)
#pragma unroll
                for (int c = 0; c < 8; c++)
                    acc[i][c] = fmaf(pr[i], vv[c], acc[i][c]);
        }
    }
    __syncthreads();

    // ---- epilogue: normalize, write to [b,s,D]
#pragma unroll
    for (int i = 0; i < 4; i++) {
        int r = ty*4 + i;
        float invl = 1.0f / row_l[r];
        float* dst = O + ((size_t)(b*SEQ + q0 + r))*DMODEL + h*DKH + tx*8;
#pragma unroll
        for (int c = 0; c < 8; c++) dst[c] = acc[i][c] * invl;
    }
}

// ---------------------------------------------------------------------------
extern "C" void kernel_launch(void* const* d_in, const int* in_sizes, int n_in,
                              void* d_out, int out_size)
{
    const float* x  = (const float*)d_in[0];
    // d_in[1] = token_positions (== arange(SEQ), used implicitly)
    const float* wq = (const float*)d_in[2];
    const float* wk = (const float*)d_in[3];
    const float* wv = (const float*)d_in[4];
    const float* wo = (const float*)d_in[5];
    float* out = (float*)d_out;

    float *q, *k, *v, *ao;
    cudaGetSymbolAddress((void**)&q,  g_Q);
    cudaGetSymbolAddress((void**)&k,  g_K);
    cudaGetSymbolAddress((void**)&v,  g_V);
    cudaGetSymbolAddress((void**)&ao, g_AO);

    cudaFuncSetAttribute(flash_kernel, cudaFuncAttributeMaxDynamicSharedMemorySize,
                         FLASH_SMEM_FLOATS * (int)sizeof(float));

    dim3 ggrid(DMODEL/128, MROWS/128);   // (16, 32)
    gemm_tf32<true><<<ggrid, 256>>>(x, wq, q);
    gemm_tf32<true><<<ggrid, 256>>>(x, wk, k);
    gemm_tf32<true><<<ggrid, 256>>>(x, wv, v);

    int npairs = BATCH*HEADS*SEQ*(DKH/2);
    rope_kernel<<<(npairs + 255)/256, 256>>>(q);
    rope_kernel<<<(npairs + 255)/256, 256>>>(k);

    dim3 fgrid(SEQ/64, BATCH*HEADS);     // (32, 32)
    flash_kernel<<<fgrid, 256, FLASH_SMEM_FLOATS * sizeof(float)>>>(q, k, v, ao);

    gemm_tf32<false><<<ggrid, 256>>>(ao, wo, out);
}

// round 3
// speedup vs baseline: 1.8126x; 1.8126x over previous
#include <cuda_runtime.h>
#include <cuda_fp16.h>
#include <cuda_bf16.h>
#include <mma.h>
#include <math.h>
#include <cstdint>

using namespace nvcuda;

#define BATCH   2
#define SEQ     2048
#define DMODEL  2048
#define HEADS   16
#define DKH     128
#define MROWS   (BATCH*SEQ)

// ---------------- scratch (__device__ globals; allocation-free rule) -------
__device__ float  g_Q [BATCH*HEADS*SEQ*DKH];
__device__ float  g_K [BATCH*HEADS*SEQ*DKH];
__device__ float  g_V [BATCH*HEADS*SEQ*DKH];
__device__ float  g_AO[BATCH*SEQ*DMODEL];
__device__ __half g_xh [MROWS*DMODEL];        // fp16 input
__device__ __half g_wqh[DMODEL*DMODEL];
__device__ __half g_wkh[DMODEL*DMODEL];
__device__ __half g_wvh[DMODEL*DMODEL];
__device__ __half g_woh[DMODEL*DMODEL];
__device__ __half g_aoh[MROWS*DMODEL];        // fp16 attention output

// ---------------------------------------------------------------------------
// fp32 -> fp16 convert (vectorized)
// ---------------------------------------------------------------------------
__global__ void f32_to_f16(const float* __restrict__ in, __half* __restrict__ out, int n4)
{
    int i = blockIdx.x * blockDim.x + threadIdx.x;
    if (i >= n4) return;
    float4 v = *(const float4*)(in + (size_t)i*4);
    __half2 a = __floats2half2_rn(v.x, v.y);
    __half2 b = __floats2half2_rn(v.z, v.w);
    *(__half2*)(out + (size_t)i*4)     = a;
    *(__half2*)(out + (size_t)i*4 + 2) = b;
}

// ---------------------------------------------------------------------------
// cp.async helpers
// ---------------------------------------------------------------------------
__device__ __forceinline__ void cp_async16(void* smem, const void* gmem)
{
    unsigned int s = (unsigned int)__cvta_generic_to_shared(smem);
    asm volatile("cp.async.cg.shared.global [%0], [%1], 16;\n" :: "r"(s), "l"(gmem));
}
__device__ __forceinline__ void cp_commit() { asm volatile("cp.async.commit_group;\n"); }
template<int N> __device__ __forceinline__ void cp_wait() { asm volatile("cp.async.wait_group %0;\n" :: "n"(N)); }

// ---------------------------------------------------------------------------
// fp16 WMMA GEMM, 4-stage cp.async pipeline.
//   C[m,n] = sum_k A[m,k] * W[n,k]   (A [M,2048] f16 rm, W [2048,2048] f16 rm)
// QKV=true: blockIdx.z in {0,1,2} picks (W,C) pair; output scattered headwise.
// ---------------------------------------------------------------------------
#define GSTAGES 4
#define GBK     32
#define GAP     40                          // halves per smem row (32 + 8 pad)
#define GSTAGE_HALVES (2*128*GAP)           // A tile + B tile per stage
#define GEMM_SMEM_BYTES (GSTAGES*GSTAGE_HALVES*(int)sizeof(__half))

template<bool QKV>
__global__ __launch_bounds__(256, 2)
void gemm_f16(const __half* __restrict__ A,
              const __half* __restrict__ W0, const __half* __restrict__ W1, const __half* __restrict__ W2,
              float* __restrict__ C0, float* __restrict__ C1, float* __restrict__ C2)
{
    extern __shared__ __half sm_h[];

    const __half* W = W0;
    float* C = C0;
    if (QKV) {
        if (blockIdx.z == 1) { W = W1; C = C1; }
        else if (blockIdx.z == 2) { W = W2; C = C2; }
    }

    const int m0  = blockIdx.y * 128;
    const int n0  = blockIdx.x * 128;
    const int tid = threadIdx.x;
    const int wid = tid >> 5;
    const int wm  = wid & 1;
    const int wn  = wid >> 1;

    wmma::fragment<wmma::accumulator,16,16,16,float> c[4][2];
#pragma unroll
    for (int i = 0; i < 4; i++)
#pragma unroll
        for (int j = 0; j < 2; j++)
            wmma::fill_fragment(c[i][j], 0.0f);

    const int NT = 2048 / GBK;              // 64 k-tiles

    auto load_stage = [&](int kt) {
        __half* sA = sm_h + (kt & (GSTAGES-1)) * GSTAGE_HALVES;
        __half* sB = sA + 128*GAP;
        const int kbase = kt * GBK;
#pragma unroll
        for (int it = 0; it < 2; it++) {
            int idx = it*256 + tid;          // 512 chunks of 16B
            int row = idx >> 2, cc = idx & 3;
            cp_async16(&sA[row*GAP + cc*8], A + (size_t)(m0+row)*2048 + kbase + cc*8);
        }
#pragma unroll
        for (int it = 0; it < 2; it++) {
            int idx = it*256 + tid;
            int row = idx >> 2, cc = idx & 3;
            cp_async16(&sB[row*GAP + cc*8], W + (size_t)(n0+row)*2048 + kbase + cc*8);
        }
    };

    // prologue: 3 stages in flight
#pragma unroll
    for (int s = 0; s < GSTAGES-1; s++) { load_stage(s); cp_commit(); }

    for (int kt = 0; kt < NT; kt++) {
        cp_wait<GSTAGES-2>();
        __syncthreads();
        if (kt + GSTAGES-1 < NT) load_stage(kt + GSTAGES-1);
        cp_commit();

        __half* sA = sm_h + (kt & (GSTAGES-1)) * GSTAGE_HALVES;
        __half* sB = sA + 128*GAP;
#pragma unroll
        for (int ks = 0; ks < 2; ks++) {
            wmma::fragment<wmma::matrix_a,16,16,16,__half,wmma::row_major> a[4];
            wmma::fragment<wmma::matrix_b,16,16,16,__half,wmma::col_major> b[2];
#pragma unroll
            for (int i = 0; i < 4; i++)
                wmma::load_matrix_sync(a[i], &sA[(wm*64 + i*16)*GAP + ks*16], GAP);
#pragma unroll
            for (int j = 0; j < 2; j++)
                wmma::load_matrix_sync(b[j], &sB[(wn*32 + j*16)*GAP + ks*16], GAP);
#pragma unroll
            for (int i = 0; i < 4; i++)
#pragma unroll
                for (int j = 0; j < 2; j++)
                    wmma::mma_sync(c[i][j], a[i], b[j], c[i][j]);
        }
    }

    if (QKV) {
        const int b  = m0 / SEQ;
        const int s0 = m0 % SEQ;
        const int h  = blockIdx.x;
        float* base = C + ((size_t)(b*HEADS + h)*SEQ + s0) * DKH;
#pragma unroll
        for (int i = 0; i < 4; i++)
#pragma unroll
            for (int j = 0; j < 2; j++)
                wmma::store_matrix_sync(base + (size_t)(wm*64 + i*16)*DKH + wn*32 + j*16,
                                        c[i][j], DKH, wmma::mem_row_major);
    } else {
        float* base = C + (size_t)m0*DMODEL + n0;
#pragma unroll
        for (int i = 0; i < 4; i++)
#pragma unroll
            for (int j = 0; j < 2; j++)
                wmma::store_matrix_sync(base + (size_t)(wm*64 + i*16)*DMODEL + wn*32 + j*16,
                                        c[i][j], DMODEL, wmma::mem_row_major);
    }
}

// ---------------------------------------------------------------------------
// RoPE in place on [b,h,s,dk] tensor. positions == s by construction.
// ---------------------------------------------------------------------------
__global__ void rope_kernel(float* __restrict__ X)
{
    int idx = blockIdx.x * blockDim.x + threadIdx.x;
    if (idx >= BATCH*HEADS*SEQ*(DKH/2)) return;
    int dd = idx & 63;
    int s  = (idx >> 6) & (SEQ - 1);
    float freq = exp2f(-13.287712379549449f * ((float)(2*dd) * (1.0f/128.0f)));
    float ang  = (float)s * freq;
    float sn, cs;
    sincosf(ang, &sn, &cs);
    float* p = X + (size_t)idx * 2;
    float x1 = p[0], x2 = p[1];
    p[0] = x1*cs - x2*sn;
    p[1] = x1*sn + x2*cs;
}

// ---------------------------------------------------------------------------
// Flash attention (causal), fp32 — unchanged (known-correct baseline).
// ---------------------------------------------------------------------------
#define FPAD  68
#define VPAD  132
#define FLASH_SMEM_FLOATS (128*FPAD*2 + 64*VPAD + 64*FPAD + 3*64)

__global__ __launch_bounds__(256)
void flash_kernel(const float* __restrict__ Q, const float* __restrict__ K,
                  const float* __restrict__ V, float* __restrict__ O)
{
    extern __shared__ float sm[];
    float* QsT  = sm;
    float* KsT  = QsT + 128*FPAD;
    float* Vs   = KsT + 128*FPAD;
    float* Ss   = Vs  + 64*VPAD;
    float* row_m  = Ss + 64*FPAD;
    float* row_l  = row_m + 64;
    float* row_al = row_l + 64;

    const int qt  = gridDim.x - 1 - blockIdx.x;
    const int bh  = blockIdx.y;
    const int b   = bh >> 4;
    const int h   = bh & 15;
    const int q0  = qt * 64;
    const int tid = threadIdx.x;
    const int ty  = tid >> 4;
    const int tx  = tid & 15;

    const float* Qb = Q + ((size_t)bh * SEQ + q0) * DKH;
    for (int i = tid; i < 64*32; i += 256) {
        int r = i >> 5, c4 = i & 31;
        float4 v = *(const float4*)(Qb + (size_t)r*DKH + c4*4);
        QsT[(c4*4+0)*FPAD + r] = v.x;
        QsT[(c4*4+1)*FPAD + r] = v.y;
        QsT[(c4*4+2)*FPAD + r] = v.z;
        QsT[(c4*4+3)*FPAD + r] = v.w;
    }
    if (tid < 64) { row_m[tid] = -INFINITY; row_l[tid] = 0.0f; }

    float acc[4][8];
#pragma unroll
    for (int i = 0; i < 4; i++)
#pragma unroll
        for (int c = 0; c < 8; c++) acc[i][c] = 0.0f;

    const float SCALE = 0.08838834764831845f;
    const int ntiles = qt + 1;

    for (int t = 0; t < ntiles; t++) {
        const int k0 = t * 64;
        __syncthreads();
        const float* Kb = K + ((size_t)bh * SEQ + k0) * DKH;
        const float* Vb = V + ((size_t)bh * SEQ + k0) * DKH;
        for (int i = tid; i < 64*32; i += 256) {
            int r = i >> 5, c4 = i & 31;
            float4 kv = *(const float4*)(Kb + (size_t)r*DKH + c4*4);
            KsT[(c4*4+0)*FPAD + r] = kv.x;
            KsT[(c4*4+1)*FPAD + r] = kv.y;
            KsT[(c4*4+2)*FPAD + r] = kv.z;
            KsT[(c4*4+3)*FPAD + r] = kv.w;
            float4 vv = *(const float4*)(Vb + (size_t)r*DKH + c4*4);
            *(float4*)&Vs[r*VPAD + c4*4] = vv;
        }
        __syncthreads();

        float sa[4][4];
#pragma unroll
        for (int i = 0; i < 4; i++)
#pragma unroll
            for (int j = 0; j < 4; j++) sa[i][j] = 0.0f;

#pragma unroll 4
        for (int k = 0; k < DKH; k++) {
            float qr[4], kr[4];
#pragma unroll
            for (int i = 0; i < 4; i++) qr[i] = QsT[k*FPAD + ty*4 + i];
#pragma unroll
            for (int j = 0; j < 4; j++) kr[j] = KsT[k*FPAD + tx*4 + j];
#pragma unroll
            for (int i = 0; i < 4; i++)
#pragma unroll
                for (int j = 0; j < 4; j++)
                    sa[i][j] = fmaf(qr[i], kr[j], sa[i][j]);
        }
        const bool diag = (t == ntiles - 1) && (k0 == q0);
#pragma unroll
        for (int i = 0; i < 4; i++) {
            int gi = ty*4 + i;
#pragma unroll
            for (int j = 0; j < 4; j++) {
                int gj = tx*4 + j;
                float sv = sa[i][j] * SCALE;
                if (diag && (gj > gi)) sv = -INFINITY;
                Ss[gi*FPAD + gj] = sv;
            }
        }
        __syncthreads();

        {
            int r   = tid >> 2;
            int seg = tid & 3;
            float vals[16];
            float lm = -INFINITY;
#pragma unroll
            for (int j = 0; j < 16; j++) {
                vals[j] = Ss[r*FPAD + seg*16 + j];
                lm = fmaxf(lm, vals[j]);
            }
            lm = fmaxf(lm, __shfl_xor_sync(0xffffffffu, lm, 1));
            lm = fmaxf(lm, __shfl_xor_sync(0xffffffffu, lm, 2));
            float m_old = row_m[r];
            float m_new = fmaxf(m_old, lm);
            float lsum = 0.0f;
#pragma unroll
            for (int j = 0; j < 16; j++) {
                float p = __expf(vals[j] - m_new);
                Ss[r*FPAD + seg*16 + j] = p;
                lsum += p;
            }
            lsum += __shfl_xor_sync(0xffffffffu, lsum, 1);
            lsum += __shfl_xor_sync(0xffffffffu, lsum, 2);
            if (seg == 0) {
                float al = __expf(m_old - m_new);
                row_al[r] = al;
                row_m[r]  = m_new;
                row_l[r]  = row_l[r] * al + lsum;
            }
        }
        __syncthreads();

#pragma unroll
        for (int i = 0; i < 4; i++) {
            float al = row_al[ty*4 + i];
#pragma unroll
            for (int c = 0; c < 8; c++) acc[i][c] *= al;
        }
#pragma unroll 2
        for (int j = 0; j < 64; j++) {
            float pr[4];
#pragma unroll
            for (int i = 0; i < 4; i++) pr[i] = Ss[(ty*4 + i)*FPAD + j];
            float4 v0 = *(const float4*)&Vs[j*VPAD + tx*8];
            float4 v1 = *(const float4*)&Vs[j*VPAD + tx*8 + 4];
            float vv[8] = {v0.x, v0.y, v0.z, v0.w, v1.x, v1.y, v1.z, v1.w};
#pragma unroll
            for (int i = 0; i < 4; i++)
#pragma unroll
                for (int c = 0; c < 8; c++)
                    acc[i][c] = fmaf(pr[i], vv[c], acc[i][c]);
        }
    }
    __syncthreads();

#pragma unroll
    for (int i = 0; i < 4; i++) {
        int r = ty*4 + i;
        float invl = 1.0f / row_l[r];
        float* dst = O + ((size_t)(b*SEQ + q0 + r))*DMODEL + h*DKH + tx*8;
#pragma unroll
        for (int c = 0; c < 8; c++) dst[c] = acc[i][c] * invl;
    }
}

// ---------------------------------------------------------------------------
extern "C" void kernel_launch(void* const* d_in, const int* in_sizes, int n_in,
                              void* d_out, int out_size)
{
    const float* x  = (const float*)d_in[0];
    const float* wq = (const float*)d_in[2];
    const float* wk = (const float*)d_in[3];
    const float* wv = (const float*)d_in[4];
    const float* wo = (const float*)d_in[5];
    float* out = (float*)d_out;

    float *q, *k, *v, *ao;
    __half *xh, *wqh, *wkh, *wvh, *woh, *aoh;
    cudaGetSymbolAddress((void**)&q,   g_Q);
    cudaGetSymbolAddress((void**)&k,   g_K);
    cudaGetSymbolAddress((void**)&v,   g_V);
    cudaGetSymbolAddress((void**)&ao,  g_AO);
    cudaGetSymbolAddress((void**)&xh,  g_xh);
    cudaGetSymbolAddress((void**)&wqh, g_wqh);
    cudaGetSymbolAddress((void**)&wkh, g_wkh);
    cudaGetSymbolAddress((void**)&wvh, g_wvh);
    cudaGetSymbolAddress((void**)&woh, g_woh);
    cudaGetSymbolAddress((void**)&aoh, g_aoh);

    cudaFuncSetAttribute(gemm_f16<true>,  cudaFuncAttributeMaxDynamicSharedMemorySize, GEMM_SMEM_BYTES);
    cudaFuncSetAttribute(gemm_f16<false>, cudaFuncAttributeMaxDynamicSharedMemorySize, GEMM_SMEM_BYTES);
    cudaFuncSetAttribute(flash_kernel, cudaFuncAttributeMaxDynamicSharedMemorySize,
                         FLASH_SMEM_FLOATS * (int)sizeof(float));

    // converts
    {
        int n4x = MROWS*DMODEL/4;      // 2M float4
        int n4w = DMODEL*DMODEL/4;     // 1M
        f32_to_f16<<<(n4x+255)/256, 256>>>(x,  xh,  n4x);
        f32_to_f16<<<(n4w+255)/256, 256>>>(wq, wqh, n4w);
        f32_to_f16<<<(n4w+255)/256, 256>>>(wk, wkh, n4w);
        f32_to_f16<<<(n4w+255)/256, 256>>>(wv, wvh, n4w);
        f32_to_f16<<<(n4w+255)/256, 256>>>(wo, woh, n4w);
    }

    // fused QKV projection
    dim3 qkv_grid(DMODEL/128, MROWS/128, 3);
    gemm_f16<true><<<qkv_grid, 256, GEMM_SMEM_BYTES>>>(xh, wqh, wkh, wvh, q, k, v);

    int npairs = BATCH*HEADS*SEQ*(DKH/2);
    rope_kernel<<<(npairs + 255)/256, 256>>>(q);
    rope_kernel<<<(npairs + 255)/256, 256>>>(k);

    dim3 fgrid(SEQ/64, BATCH*HEADS);
    flash_kernel<<<fgrid, 256, FLASH_SMEM_FLOATS * sizeof(float)>>>(q, k, v, ao);

    // AO -> fp16, then output projection
    {
        int n4 = MROWS*DMODEL/4;
        f32_to_f16<<<(n4+255)/256, 256>>>(ao, aoh, n4);
    }
    dim3 wo_grid(DMODEL/128, MROWS/128, 1);
    gemm_f16<false><<<wo_grid, 256, GEMM_SMEM_BYTES>>>(aoh, woh, nullptr, nullptr,
                                                       out, nullptr, nullptr);
}

// round 4
// speedup vs baseline: 5.6870x; 3.1375x over previous
#include <cuda_runtime.h>
#include <cuda_fp16.h>
#include <cuda_bf16.h>
#include <mma.h>
#include <math.h>
#include <cstdint>

using namespace nvcuda;

#define BATCH   2
#define SEQ     2048
#define DMODEL  2048
#define HEADS   16
#define DKH     128
#define MROWS   (BATCH*SEQ)

// ---------------- scratch (__device__ globals; allocation-free rule) -------
__device__ float  g_Q [BATCH*HEADS*SEQ*DKH];
__device__ float  g_K [BATCH*HEADS*SEQ*DKH];
__device__ float  g_V [BATCH*HEADS*SEQ*DKH];
__device__ __half g_Qh[BATCH*HEADS*SEQ*DKH];
__device__ __half g_Kh[BATCH*HEADS*SEQ*DKH];
__device__ __half g_Vh[BATCH*HEADS*SEQ*DKH];
__device__ __half g_xh [MROWS*DMODEL];
__device__ __half g_wqh[DMODEL*DMODEL];
__device__ __half g_wkh[DMODEL*DMODEL];
__device__ __half g_wvh[DMODEL*DMODEL];
__device__ __half g_woh[DMODEL*DMODEL];
__device__ __half g_aoh[MROWS*DMODEL];

// ---------------------------------------------------------------------------
__global__ void f32_to_f16(const float* __restrict__ in, __half* __restrict__ out, int n4)
{
    int i = blockIdx.x * blockDim.x + threadIdx.x;
    if (i >= n4) return;
    float4 v = *(const float4*)(in + (size_t)i*4);
    *(__half2*)(out + (size_t)i*4)     = __floats2half2_rn(v.x, v.y);
    *(__half2*)(out + (size_t)i*4 + 2) = __floats2half2_rn(v.z, v.w);
}

// ---------------------------------------------------------------------------
__device__ __forceinline__ void cp_async16(void* smem, const void* gmem)
{
    unsigned int s = (unsigned int)__cvta_generic_to_shared(smem);
    asm volatile("cp.async.cg.shared.global [%0], [%1], 16;\n" :: "r"(s), "l"(gmem));
}
__device__ __forceinline__ void cp_commit() { asm volatile("cp.async.commit_group;\n"); }
template<int N> __device__ __forceinline__ void cp_wait() { asm volatile("cp.async.wait_group %0;\n" :: "n"(N)); }

__device__ __forceinline__ unsigned int smaddr(const void* p)
{ return (unsigned int)__cvta_generic_to_shared(p); }

__device__ __forceinline__ void ldsm4(uint32_t* r, unsigned int a)
{
    asm volatile("ldmatrix.sync.aligned.m8n8.x4.shared.b16 {%0,%1,%2,%3}, [%4];"
                 : "=r"(r[0]), "=r"(r[1]), "=r"(r[2]), "=r"(r[3]) : "r"(a));
}
__device__ __forceinline__ void ldsm4t(uint32_t* r, unsigned int a)
{
    asm volatile("ldmatrix.sync.aligned.m8n8.x4.trans.shared.b16 {%0,%1,%2,%3}, [%4];"
                 : "=r"(r[0]), "=r"(r[1]), "=r"(r[2]), "=r"(r[3]) : "r"(a));
}
__device__ __forceinline__ void mma16816(float* d, const uint32_t* a, const uint32_t* b)
{
    asm volatile("mma.sync.aligned.m16n8k16.row.col.f32.f16.f16.f32 "
                 "{%0,%1,%2,%3},{%4,%5,%6,%7},{%8,%9},{%0,%1,%2,%3};"
                 : "+f"(d[0]), "+f"(d[1]), "+f"(d[2]), "+f"(d[3])
                 : "r"(a[0]), "r"(a[1]), "r"(a[2]), "r"(a[3]), "r"(b[0]), "r"(b[1]));
}

// ---------------------------------------------------------------------------
// fp16 WMMA GEMM, 4-stage cp.async pipeline (unchanged from R3 — known good)
// ---------------------------------------------------------------------------
#define GSTAGES 4
#define GBK     32
#define GAP     40
#define GSTAGE_HALVES (2*128*GAP)
#define GEMM_SMEM_BYTES (GSTAGES*GSTAGE_HALVES*(int)sizeof(__half))

template<bool QKV>
__global__ __launch_bounds__(256, 2)
void gemm_f16(const __half* __restrict__ A,
              const __half* __restrict__ W0, const __half* __restrict__ W1, const __half* __restrict__ W2,
              float* __restrict__ C0, float* __restrict__ C1, float* __restrict__ C2)
{
    extern __shared__ __half sm_h[];

    const __half* W = W0;
    float* C = C0;
    if (QKV) {
        if (blockIdx.z == 1) { W = W1; C = C1; }
        else if (blockIdx.z == 2) { W = W2; C = C2; }
    }

    const int m0  = blockIdx.y * 128;
    const int n0  = blockIdx.x * 128;
    const int tid = threadIdx.x;
    const int wid = tid >> 5;
    const int wm  = wid & 1;
    const int wn  = wid >> 1;

    wmma::fragment<wmma::accumulator,16,16,16,float> c[4][2];
#pragma unroll
    for (int i = 0; i < 4; i++)
#pragma unroll
        for (int j = 0; j < 2; j++)
            wmma::fill_fragment(c[i][j], 0.0f);

    const int NT = 2048 / GBK;

    auto load_stage = [&](int kt) {
        __half* sA = sm_h + (kt & (GSTAGES-1)) * GSTAGE_HALVES;
        __half* sB = sA + 128*GAP;
        const int kbase = kt * GBK;
#pragma unroll
        for (int it = 0; it < 2; it++) {
            int idx = it*256 + tid;
            int row = idx >> 2, cc = idx & 3;
            cp_async16(&sA[row*GAP + cc*8], A + (size_t)(m0+row)*2048 + kbase + cc*8);
        }
#pragma unroll
        for (int it = 0; it < 2; it++) {
            int idx = it*256 + tid;
            int row = idx >> 2, cc = idx & 3;
            cp_async16(&sB[row*GAP + cc*8], W + (size_t)(n0+row)*2048 + kbase + cc*8);
        }
    };

#pragma unroll
    for (int s = 0; s < GSTAGES-1; s++) { load_stage(s); cp_commit(); }

    for (int kt = 0; kt < NT; kt++) {
        cp_wait<GSTAGES-2>();
        __syncthreads();
        if (kt + GSTAGES-1 < NT) load_stage(kt + GSTAGES-1);
        cp_commit();

        __half* sA = sm_h + (kt & (GSTAGES-1)) * GSTAGE_HALVES;
        __half* sB = sA + 128*GAP;
#pragma unroll
        for (int ks = 0; ks < 2; ks++) {
            wmma::fragment<wmma::matrix_a,16,16,16,__half,wmma::row_major> a[4];
            wmma::fragment<wmma::matrix_b,16,16,16,__half,wmma::col_major> b[2];
#pragma unroll
            for (int i = 0; i < 4; i++)
                wmma::load_matrix_sync(a[i], &sA[(wm*64 + i*16)*GAP + ks*16], GAP);
#pragma unroll
            for (int j = 0; j < 2; j++)
                wmma::load_matrix_sync(b[j], &sB[(wn*32 + j*16)*GAP + ks*16], GAP);
#pragma unroll
            for (int i = 0; i < 4; i++)
#pragma unroll
                for (int j = 0; j < 2; j++)
                    wmma::mma_sync(c[i][j], a[i], b[j], c[i][j]);
        }
    }

    if (QKV) {
        const int b  = m0 / SEQ;
        const int s0 = m0 % SEQ;
        const int h  = blockIdx.x;
        float* base = C + ((size_t)(b*HEADS + h)*SEQ + s0) * DKH;
#pragma unroll
        for (int i = 0; i < 4; i++)
#pragma unroll
            for (int j = 0; j < 2; j++)
                wmma::store_matrix_sync(base + (size_t)(wm*64 + i*16)*DKH + wn*32 + j*16,
                                        c[i][j], DKH, wmma::mem_row_major);
    } else {
        float* base = C + (size_t)m0*DMODEL + n0;
#pragma unroll
        for (int i = 0; i < 4; i++)
#pragma unroll
            for (int j = 0; j < 2; j++)
                wmma::store_matrix_sync(base + (size_t)(wm*64 + i*16)*DMODEL + wn*32 + j*16,
                                        c[i][j], DMODEL, wmma::mem_row_major);
    }
}

// ---------------------------------------------------------------------------
// RoPE fp32 -> fp16 (scale folded in for Q). positions == s by construction.
// ---------------------------------------------------------------------------
__global__ void rope_to_f16(const float* __restrict__ X, __half* __restrict__ Xh, float scale)
{
    int idx = blockIdx.x * blockDim.x + threadIdx.x;
    if (idx >= BATCH*HEADS*SEQ*(DKH/2)) return;
    int dd = idx & 63;
    int s  = (idx >> 6) & (SEQ - 1);
    float freq = exp2f(-13.287712379549449f * ((float)(2*dd) * (1.0f/128.0f)));
    float ang  = (float)s * freq;
    float sn, cs;
    sincosf(ang, &sn, &cs);
    const float* p = X + (size_t)idx * 2;
    float x1 = p[0], x2 = p[1];
    float y1 = (x1*cs - x2*sn) * scale;
    float y2 = (x1*sn + x2*cs) * scale;
    *(__half2*)(Xh + (size_t)idx*2) = __floats2half2_rn(y1, y2);
}

// ---------------------------------------------------------------------------
// FA2-style fp16 flash attention (causal). Br=128, Bc=64, d=128, 8 warps.
// Q fragments register-resident; S-acc -> P-frag conversion in registers.
// Writes AO as fp16 [b, s, h*128+d].
// ---------------------------------------------------------------------------
#define BR 128
#define BC 64
#define DPAD 136                              // halves per smem row (128 + 8)
#define KV_STAGE_HALVES (2*BC*DPAD)           // K tile + V tile
#define FL_SMEM_BYTES (2*KV_STAGE_HALVES*(int)sizeof(__half))

__global__ __launch_bounds__(256, 1)
void flash16(const __half* __restrict__ Q, const __half* __restrict__ K,
             const __half* __restrict__ V, __half* __restrict__ AO)
{
    extern __shared__ __half smf[];
    __half* buf0 = smf;                       // stage 0
    __half* buf1 = smf + KV_STAGE_HALVES;     // stage 1 (doubles as Q staging)

    const int qt  = (gridDim.x - 1) - blockIdx.x;    // heavy tiles first
    const int bh  = blockIdx.y;
    const int q0  = qt * BR;
    const int tid = threadIdx.x;
    const int lane = tid & 31;
    const int wid  = tid >> 5;
    const int g    = lane >> 2;
    const int t4   = lane & 3;
    const int l8   = lane & 7;

    // ---- Q -> smem (buf1) -> register fragments
    const __half* Qg = Q + ((size_t)bh * SEQ + q0) * DKH;
    for (int i = tid; i < BR*16; i += 256) {
        int r = i >> 4, c = i & 15;
        cp_async16(&buf1[r*DPAD + c*8], Qg + (size_t)r*DKH + c*8);
    }
    cp_commit();
    cp_wait<0>();
    __syncthreads();

    uint32_t qf[8][4];
    {
        int row  = wid*16 + ((lane >> 3) & 1)*8 + l8;
        int koff = (lane >> 4) * 8;
#pragma unroll
        for (int ks = 0; ks < 8; ks++)
            ldsm4(qf[ks], smaddr(&buf1[row*DPAD + ks*16 + koff]));
    }
    __syncthreads();   // everyone done reading buf1 before KV loads reuse it

    float o[16][4];
#pragma unroll
    for (int i = 0; i < 16; i++)
#pragma unroll
        for (int j = 0; j < 4; j++) o[i][j] = 0.0f;
    float m1 = -1e30f, m2 = -1e30f, l1 = 0.0f, l2 = 0.0f;

    auto loadKV = [&](int t, int stage) {
        const __half* Kg = K + ((size_t)bh * SEQ + t*BC) * DKH;
        const __half* Vg = V + ((size_t)bh * SEQ + t*BC) * DKH;
        __half* s  = stage ? buf1 : buf0;
        __half* sv = s + BC*DPAD;
#pragma unroll
        for (int it = 0; it < 4; it++) {
            int i = it*256 + tid;
            int r = i >> 4, c = i & 15;
            cp_async16(&s[r*DPAD + c*8],  Kg + (size_t)r*DKH + c*8);
        }
#pragma unroll
        for (int it = 0; it < 4; it++) {
            int i = it*256 + tid;
            int r = i >> 4, c = i & 15;
            cp_async16(&sv[r*DPAD + c*8], Vg + (size_t)r*DKH + c*8);
        }
    };

    const int nt = 2*qt + 2;
    loadKV(0, 0);
    cp_commit();

    for (int t = 0; t < nt; t++) {
        if (t + 1 < nt) { loadKV(t+1, (t+1) & 1); cp_commit(); cp_wait<1>(); }
        else            { cp_wait<0>(); }
        __syncthreads();

        __half* sk = (t & 1) ? buf1 : buf0;
        __half* sv = sk + BC*DPAD;

        // ---- S = Q K^T  (16 rows x 64 cols per warp)
        float s[8][4];
#pragma unroll
        for (int i = 0; i < 8; i++)
#pragma unroll
            for (int j = 0; j < 4; j++) s[i][j] = 0.0f;

#pragma unroll
        for (int ks = 0; ks < 8; ks++) {
#pragma unroll
            for (int nb2 = 0; nb2 < 4; nb2++) {
                uint32_t kf[4];
                int row  = nb2*16 + ((lane >> 4) & 1)*8 + l8;
                int koff = ks*16 + ((lane >> 3) & 1)*8;
                ldsm4(kf, smaddr(&sk[row*DPAD + koff]));
                mma16816(s[nb2*2],     qf[ks], kf);
                mma16816(s[nb2*2 + 1], qf[ks], kf + 2);
            }
        }

        // ---- causal mask (only the last two tiles can cross the diagonal)
        if (t >= 2*qt) {
            int row1 = q0 + wid*16 + g;
            int row2 = row1 + 8;
            int cb   = t*BC + t4*2;
#pragma unroll
            for (int nb = 0; nb < 8; nb++) {
                int c0 = cb + nb*8, c1 = c0 + 1;
                if (c0 > row1) s[nb][0] = -1e30f;
                if (c1 > row1) s[nb][1] = -1e30f;
                if (c0 > row2) s[nb][2] = -1e30f;
                if (c1 > row2) s[nb][3] = -1e30f;
            }
        }

        // ---- online softmax (rows g and g+8; 4 lanes per row)
        float mx1 = -1e30f, mx2 = -1e30f;
#pragma unroll
        for (int nb = 0; nb < 8; nb++) {
            mx1 = fmaxf(mx1, fmaxf(s[nb][0], s[nb][1]));
            mx2 = fmaxf(mx2, fmaxf(s[nb][2], s[nb][3]));
        }
        mx1 = fmaxf(mx1, __shfl_xor_sync(0xffffffffu, mx1, 1));
        mx1 = fmaxf(mx1, __shfl_xor_sync(0xffffffffu, mx1, 2));
        mx2 = fmaxf(mx2, __shfl_xor_sync(0xffffffffu, mx2, 1));
        mx2 = fmaxf(mx2, __shfl_xor_sync(0xffffffffu, mx2, 2));

        float m1n = fmaxf(m1, mx1);
        float m2n = fmaxf(m2, mx2);
        float a1  = __expf(m1 - m1n);
        float a2  = __expf(m2 - m2n);

        uint32_t pf[4][4];
        float ls1 = 0.0f, ls2 = 0.0f;
#pragma unroll
        for (int nb = 0; nb < 8; nb++) {
            float p0 = __expf(s[nb][0] - m1n);
            float p1 = __expf(s[nb][1] - m1n);
            float p2 = __expf(s[nb][2] - m2n);
            float p3 = __expf(s[nb][3] - m2n);
            ls1 += p0 + p1;
            ls2 += p2 + p3;
            __half2 h01 = __floats2half2_rn(p0, p1);
            __half2 h23 = __floats2half2_rn(p2, p3);
            int ks = nb >> 1;
            if ((nb & 1) == 0) {
                pf[ks][0] = *(uint32_t*)&h01;
                pf[ks][1] = *(uint32_t*)&h23;
            } else {
                pf[ks][2] = *(uint32_t*)&h01;
                pf[ks][3] = *(uint32_t*)&h23;
            }
        }
        ls1 += __shfl_xor_sync(0xffffffffu, ls1, 1);
        ls1 += __shfl_xor_sync(0xffffffffu, ls1, 2);
        ls2 += __shfl_xor_sync(0xffffffffu, ls2, 1);
        ls2 += __shfl_xor_sync(0xffffffffu, ls2, 2);

        l1 = l1*a1 + ls1;
        l2 = l2*a2 + ls2;
        m1 = m1n; m2 = m2n;

#pragma unroll
        for (int nb2 = 0; nb2 < 16; nb2++) {
            o[nb2][0] *= a1; o[nb2][1] *= a1;
            o[nb2][2] *= a2; o[nb2][3] *= a2;
        }

        // ---- O += P V
#pragma unroll
        for (int ks = 0; ks < 4; ks++) {
#pragma unroll
            for (int nbp = 0; nbp < 8; nbp++) {
                uint32_t vf[4];
                int row  = ks*16 + ((lane >> 4) & 1) ? 0 : 0;  // placeholder (computed below)
                (void)row;
                int vrow = ks*16 + ((lane >> 3) & 1)*8 + l8;
                int vcol = nbp*16 + (lane >> 4)*8;
                ldsm4t(vf, smaddr(&sv[vrow*DPAD + vcol]));
                mma16816(o[nbp*2],     pf[ks], vf);
                mma16816(o[nbp*2 + 1], pf[ks], vf + 2);
            }
        }

        __syncthreads();   // before next-iter loads overwrite this stage
    }

    // ---- epilogue: normalize and store fp16 AO[b, s, h*128 + d]
    const int b = bh >> 4;
    const int h = bh & 15;
    float il1 = 1.0f / l1;
    float il2 = 1.0f / l2;
    int row1 = q0 + wid*16 + g;
    int row2 = row1 + 8;
    __half* base1 = AO + ((size_t)(b*SEQ + row1))*DMODEL + h*DKH;
    __half* base2 = AO + ((size_t)(b*SEQ + row2))*DMODEL + h*DKH;
#pragma unroll
    for (int nb2 = 0; nb2 < 16; nb2++) {
        int col = nb2*8 + t4*2;
        *(__half2*)(base1 + col) = __floats2half2_rn(o[nb2][0]*il1, o[nb2][1]*il1);
        *(__half2*)(base2 + col) = __floats2half2_rn(o[nb2][2]*il2, o[nb2][3]*il2);
    }
}

// ---------------------------------------------------------------------------
extern "C" void kernel_launch(void* const* d_in, const int* in_sizes, int n_in,
                              void* d_out, int out_size)
{
    const float* x  = (const float*)d_in[0];
    const float* wq = (const float*)d_in[2];
    const float* wk = (const float*)d_in[3];
    const float* wv = (const float*)d_in[4];
    const float* wo = (const float*)d_in[5];
    float* out = (float*)d_out;

    float *q, *k, *v;
    __half *qh, *kh, *vh, *xh, *wqh, *wkh, *wvh, *woh, *aoh;
    cudaGetSymbolAddress((void**)&q,   g_Q);
    cudaGetSymbolAddress((void**)&k,   g_K);
    cudaGetSymbolAddress((void**)&v,   g_V);
    cudaGetSymbolAddress((void**)&qh,  g_Qh);
    cudaGetSymbolAddress((void**)&kh,  g_Kh);
    cudaGetSymbolAddress((void**)&vh,  g_Vh);
    cudaGetSymbolAddress((void**)&xh,  g_xh);
    cudaGetSymbolAddress((void**)&wqh, g_wqh);
    cudaGetSymbolAddress((void**)&wkh, g_wkh);
    cudaGetSymbolAddress((void**)&wvh, g_wvh);
    cudaGetSymbolAddress((void**)&woh, g_woh);
    cudaGetSymbolAddress((void**)&aoh, g_aoh);

    cudaFuncSetAttribute(gemm_f16<true>,  cudaFuncAttributeMaxDynamicSharedMemorySize, GEMM_SMEM_BYTES);
    cudaFuncSetAttribute(gemm_f16<false>, cudaFuncAttributeMaxDynamicSharedMemorySize, GEMM_SMEM_BYTES);
    cudaFuncSetAttribute(flash16, cudaFuncAttributeMaxDynamicSharedMemorySize, FL_SMEM_BYTES);

    // fp32 -> fp16 converts
    {
        int n4x = MROWS*DMODEL/4;
        int n4w = DMODEL*DMODEL/4;
        f32_to_f16<<<(n4x+255)/256, 256>>>(x,  xh,  n4x);
        f32_to_f16<<<(n4w+255)/256, 256>>>(wq, wqh, n4w);
        f32_to_f16<<<(n4w+255)/256, 256>>>(wk, wkh, n4w);
        f32_to_f16<<<(n4w+255)/256, 256>>>(wv, wvh, n4w);
        f32_to_f16<<<(n4w+255)/256, 256>>>(wo, woh, n4w);
    }

    // QKV projection (fp32 out for accurate rope input)
    dim3 qkv_grid(DMODEL/128, MROWS/128, 3);
    gemm_f16<true><<<qkv_grid, 256, GEMM_SMEM_BYTES>>>(xh, wqh, wkh, wvh, q, k, v);

    // rope + downconvert; V downconvert
    int npairs = BATCH*HEADS*SEQ*(DKH/2);
    rope_to_f16<<<(npairs + 255)/256, 256>>>(q, qh, 0.08838834764831845f);
    rope_to_f16<<<(npairs + 255)/256, 256>>>(k, kh, 1.0f);
    {
        int n4v = BATCH*HEADS*SEQ*DKH/4;
        f32_to_f16<<<(n4v+255)/256, 256>>>(v, vh, n4v);
    }

    // flash attention (fp16 in, fp16 out)
    dim3 fgrid(SEQ/BR, BATCH*HEADS);
    flash16<<<fgrid, 256, FL_SMEM_BYTES>>>(qh, kh, vh, aoh);

    // output projection
    dim3 wo_grid(DMODEL/128, MROWS/128, 1);
    gemm_f16<false><<<wo_grid, 256, GEMM_SMEM_BYTES>>>(aoh, woh, nullptr, nullptr,
                                                       out, nullptr, nullptr);
}